// round 17
// baseline (speedup 1.0000x reference)
#include <cuda_runtime.h>
#include <cstdint>

// STN bilinear sampler, v17 — LDG.256 + strip-level clamp dedup (v9 x v16).
// x: [32,256,256,32] f32 NHWC ; theta: [32,6] f32 ; out: same shape.
// 4 threads/pixel, 32B (8 floats) each; 8 rows/thread. Strip-level clamp
// classification (one vote per 8 rows; sx,sy affine in row index) skips
// address-identical gathers -> fewer DRAM read transactions interleaved in
// the write stream. 256-bit ld/st minimize instruction count.

#define B_ 32
#define H_ 256
#define W_ 256
#define ROWS_ 8
#define STEP (2.0f / 255.0f)
#define FULL 0xFFFFFFFFu

struct F8 { float v[8]; };

__device__ __forceinline__ F8 ldg256(const float* p) {
    F8 r;
    asm volatile("ld.global.nc.v8.f32 {%0,%1,%2,%3,%4,%5,%6,%7}, [%8];"
                 : "=f"(r.v[0]), "=f"(r.v[1]), "=f"(r.v[2]), "=f"(r.v[3]),
                   "=f"(r.v[4]), "=f"(r.v[5]), "=f"(r.v[6]), "=f"(r.v[7])
                 : "l"(p));
    return r;
}

__device__ __forceinline__ void stg256_cs(float* p, const F8& r) {
    asm volatile("st.global.cs.v8.f32 [%0], {%1,%2,%3,%4,%5,%6,%7,%8};"
                 :: "l"(p),
                    "f"(r.v[0]), "f"(r.v[1]), "f"(r.v[2]), "f"(r.v[3]),
                    "f"(r.v[4]), "f"(r.v[5]), "f"(r.v[6]), "f"(r.v[7])
                 : "memory");
}

struct Ctx {
    float t0, t1, t2, t3, t4, t5;
    float gx;
    int basep, co, oy, obase;
};

// MODE bit0 = x-duplicated (x0c==x1c), bit1 = y-duplicated (y0c==y1c)
template <int MODE>
__device__ __forceinline__ void run_strip(const Ctx& c,
                                          const float* __restrict__ x,
                                          float* __restrict__ out)
{
#pragma unroll
    for (int k = 0; k < ROWS_; k++) {
        float gy = -1.0f + (float)(c.oy + k) * STEP;

        // identical formula to reference: 0.5*(T·g + 1)*N, truncate toward zero
        float sx = 0.5f * (c.t0 * c.gx + c.t1 * gy + c.t2 + 1.0f) * (float)W_;
        float sy = 0.5f * (c.t3 * c.gx + c.t4 * gy + c.t5 + 1.0f) * (float)H_;

        int x0 = (int)sx;
        int y0 = (int)sy;

        int x0c = min(max(x0, 0), W_ - 1);
        int x1c = min(max(x0 + 1, 0), W_ - 1);
        int y0c = min(max(y0, 0), H_ - 1);
        int y1c = min(max(y0 + 1, 0), H_ - 1);

        float x0f = (float)x0c, x1f = (float)x1c;
        float y0f = (float)y0c, y1f = (float)y1c;

        float wa = (x1f - sx) * (y1f - sy);
        float wb = (x1f - sx) * (sy - y0f);
        float wc = (sx - x0f) * (y1f - sy);
        float wd = (sx - x0f) * (sy - y0f);

        // float-unit indices; x1 column derived via dx (0 or 32)
        int dx = (x1c - x0c) << 5;
        int ia = ((c.basep + (y0c << 8) + x0c) << 5) + c.co;
        int ib = ((c.basep + (y1c << 8) + x0c) << 5) + c.co;

        F8 pa = ldg256(x + ia);
        F8 pb, pc, pd;
        if (MODE & 2) pb = pa; else pb = ldg256(x + ib);
        if (MODE & 1) { pc = pa; pd = pb; }
        else {
            pc = ldg256(x + ia + dx);
            if (MODE & 2) pd = pc; else pd = ldg256(x + ib + dx);
        }

        F8 o;
#pragma unroll
        for (int i = 0; i < 8; i++)
            o.v[i] = wa * pa.v[i] + wb * pb.v[i]
                   + wc * pc.v[i] + wd * pd.v[i];

        stg256_cs(out + c.obase + (k << 13), o);   // + k * W_ * 32 floats
    }
}

__global__ __launch_bounds__(256) void stn_kernel(
    const float* __restrict__ x,
    const float* __restrict__ theta,
    float* __restrict__ out)
{
    int gid = blockIdx.x * blockDim.x + threadIdx.x;   // [0, 2^20)
    Ctx c;
    int h   = gid & 3;                 // 32B chunk within pixel
    int ox  = (gid >> 2) & 255;
    int oy8 = (gid >> 10) & 31;
    int b   = gid >> 15;
    c.oy = oy8 << 3;
    c.co = h << 3;

    // theta via 3x LDG.64 (8B-aligned: b*24 bytes), uniform per batch
    const float2* t2p = (const float2*)(theta + b * 6);
    float2 q0 = __ldg(t2p + 0);
    float2 q1 = __ldg(t2p + 1);
    float2 q2 = __ldg(t2p + 2);
    c.t0 = q0.x; c.t1 = q0.y; c.t2 = q1.x;
    c.t3 = q1.y; c.t4 = q2.x; c.t5 = q2.y;

    c.gx = -1.0f + (float)ox * STEP;
    c.basep = b << 16;
    c.obase = ((c.basep + (c.oy << 8) + ox) << 5) + c.co;

    // ---- strip classification via endpoint rows (sx,sy affine in oy) ----
    float gyA = -1.0f + (float)c.oy * STEP;
    float gyB = -1.0f + (float)(c.oy + ROWS_ - 1) * STEP;

    float sxA = 0.5f * (c.t0 * c.gx + c.t1 * gyA + c.t2 + 1.0f) * (float)W_;
    float syA = 0.5f * (c.t3 * c.gx + c.t4 * gyA + c.t5 + 1.0f) * (float)H_;
    float sxB = 0.5f * (c.t0 * c.gx + c.t1 * gyB + c.t2 + 1.0f) * (float)W_;
    float syB = 0.5f * (c.t3 * c.gx + c.t4 * gyB + c.t5 + 1.0f) * (float)H_;

    // conservative margins (fp rounding guard): claim dup only when certain
    bool xlo = (sxA <= -1.01f)  && (sxB <= -1.01f);
    bool xhi = (sxA >= 255.01f) && (sxB >= 255.01f);
    bool ylo = (syA <= -1.01f)  && (syB <= -1.01f);
    bool yhi = (syA >= 255.01f) && (syB >= 255.01f);

    bool ux = __all_sync(FULL, xlo) || __all_sync(FULL, xhi);
    bool uy = __all_sync(FULL, ylo) || __all_sync(FULL, yhi);

    if (ux) {
        if (uy) run_strip<3>(c, x, out);
        else    run_strip<1>(c, x, out);
    } else {
        if (uy) run_strip<2>(c, x, out);
        else    run_strip<0>(c, x, out);
    }
}

extern "C" void kernel_launch(void* const* d_in, const int* in_sizes, int n_in,
                              void* d_out, int out_size)
{
    const float* x     = (const float*)d_in[0];
    const float* theta = (const float*)d_in[1];
    float* out = (float*)d_out;

    int total_threads = B_ * (H_ / ROWS_) * W_ * 4;   // 1,048,576
    int block = 256;
    int grid = total_threads / block;                  // 4,096
    stn_kernel<<<grid, block>>>(x, theta, out);
}